// round 8
// baseline (speedup 1.0000x reference)
#include <cuda_runtime.h>
#include <cuda_bf16.h>
#include <cstdint>
#include <math_constants.h>

// Problem shapes (fixed by the dataset)
#define NQ 2048
#define NS 65536
#define KF 512          // feature dim = 32*16
#define KSEL 16         // top-k
#define NCAND 128       // candidate cap for exact refinement
#define MARGIN 1.0f     // approx-d2 margin (~7.7 sigma of bf16 error)

// GEMM tiling: CTA 128(M) x 128(N) x BK=32, 3-stage cp.async pipeline
#define BM 128
#define BN 128
#define BK 32
#define NSLABS (KF / BK)                 // 16
#define STAGES 3
#define STAGE_A_BYTES (BM * BK * 2)      // 8192
#define STAGE_B_BYTES (BN * BK * 2)      // 8192
#define STAGE_BYTES (STAGE_A_BYTES + STAGE_B_BYTES)   // 16384
#define GEMM_DYN_SMEM (STAGES * STAGE_BYTES)          // 49152

// Scratch (no cudaMalloc allowed anywhere)
__device__ float g_d2[(size_t)NQ * NS];   // approx d2 (bf16, fp32 accum)
__device__ float g_q2[NQ];
__device__ float g_s2[NS];
__device__ int   g_cand[(size_t)NQ * NCAND];
__device__ int   g_ccount[NQ];
__device__ __nv_bfloat16 g_qb[(size_t)NQ * KF];
__device__ __nv_bfloat16 g_sb[(size_t)NS * KF];

// ---------------------------------------------------------------------------
// helpers
// ---------------------------------------------------------------------------
__device__ __forceinline__ uint32_t smem_u32(const void* p) {
    uint32_t a;
    asm("{ .reg .u64 t; cvta.to.shared.u64 t, %1; cvt.u32.u64 %0, t; }"
        : "=r"(a) : "l"(p));
    return a;
}
__device__ __forceinline__ void cp16(uint32_t dst, const void* src) {
    asm volatile("cp.async.cg.shared.global [%0], [%1], 16;"
                 :: "r"(dst), "l"(src));
}
__device__ __forceinline__ void ldsm_x4(uint32_t addr, uint32_t& r0, uint32_t& r1,
                                        uint32_t& r2, uint32_t& r3) {
    asm volatile("ldmatrix.sync.aligned.m8n8.x4.shared.b16 {%0,%1,%2,%3}, [%4];"
                 : "=r"(r0), "=r"(r1), "=r"(r2), "=r"(r3) : "r"(addr));
}

// ---------------------------------------------------------------------------
// Kernel 0: fp32 -> bf16 conversion of q and s (row-major, contiguous)
// ---------------------------------------------------------------------------
__global__ void convert_kernel(const float* __restrict__ q,
                               const float* __restrict__ s) {
    size_t i = (size_t)blockIdx.x * blockDim.x + threadIdx.x;
    const size_t nq4 = (size_t)NQ * KF / 4;
    const size_t tot = nq4 + (size_t)NS * KF / 4;
    if (i >= tot) return;
    float4 v;
    __nv_bfloat16* dst;
    if (i < nq4) { v = ((const float4*)q)[i]; dst = g_qb + i * 4; }
    else { size_t j = i - nq4; v = ((const float4*)s)[j]; dst = g_sb + j * 4; }
    __nv_bfloat162 lo = __float22bfloat162_rn(make_float2(v.x, v.y));
    __nv_bfloat162 hi = __float22bfloat162_rn(make_float2(v.z, v.w));
    uint2 u;
    u.x = *reinterpret_cast<uint32_t*>(&lo);
    u.y = *reinterpret_cast<uint32_t*>(&hi);
    *reinterpret_cast<uint2*>(dst) = u;
}

// ---------------------------------------------------------------------------
// Kernel 1: squared norms (one warp per row)
// ---------------------------------------------------------------------------
__global__ void norms_kernel(const float* __restrict__ q,
                             const float* __restrict__ s) {
    int gw   = (blockIdx.x * blockDim.x + threadIdx.x) >> 5;
    int lane = threadIdx.x & 31;
    if (gw >= NQ + NS) return;
    const float* base = (gw < NQ) ? (q + (size_t)gw * KF)
                                  : (s + (size_t)(gw - NQ) * KF);
    const float4* b4 = (const float4*)base;
    float sum = 0.f;
    #pragma unroll 4
    for (int i = lane; i < KF / 4; i += 32) {
        float4 v = b4[i];
        sum += v.x * v.x + v.y * v.y + v.z * v.z + v.w * v.w;
    }
    #pragma unroll
    for (int o = 16; o; o >>= 1) sum += __shfl_down_sync(0xffffffffu, sum, o);
    if (lane == 0) {
        if (gw < NQ) g_q2[gw] = sum;
        else         g_s2[gw - NQ] = sum;
    }
}

// ---------------------------------------------------------------------------
// Kernel 2: approx d2 GEMM — mma.sync bf16, cp.async 3-stage, ldmatrix.
// grid = (NQ/BM, NS/BN) = (16, 512), M fast -> B-tile L2 reuse.
//
// smem per stage: A 128x32 bf16 (64B rows), B 128x32 bf16.
// Swizzle: 16B chunk ch at position ch ^ ((row>>1)&3). 8 consecutive rows x
// fixed ch map to 8 distinct 16B banks-groups covering all 32 banks ->
// conflict-free ldmatrix and cp.async stores.
// ---------------------------------------------------------------------------
__global__ __launch_bounds__(256)
void dist_gemm() {
    extern __shared__ __align__(16) char dynsmem[];
    const uint32_t sbase = smem_u32(dynsmem);

    const int tid  = threadIdx.x;
    const int wid  = tid >> 5;
    const int lane = tid & 31;
    const int m0 = blockIdx.x * BM;
    const int n0 = blockIdx.y * BN;
    const int wm = (wid & 1) * 64;        // warp tile 64(M) x 32(N)
    const int wn = (wid >> 1) * 32;

    // cp.async staging addresses (per thread, 2 chunks per operand per stage)
    int c0 = tid;            // 0..255
    int c1 = tid + 256;      // 256..511
    int ar0 = c0 >> 2, ac0 = c0 & 3;
    int ar1 = c1 >> 2, ac1 = c1 & 3;
    uint32_t dA0 = ar0 * 64 + ((ac0 ^ ((ar0 >> 1) & 3)) << 4);
    uint32_t dA1 = ar1 * 64 + ((ac1 ^ ((ar1 >> 1) & 3)) << 4);

    const __nv_bfloat16* Ag = g_qb + (size_t)m0 * KF;
    const __nv_bfloat16* Bg = g_sb + (size_t)n0 * KF;

    auto issue = [&](int stage, int kt) {
        uint32_t sA = sbase + stage * STAGE_BYTES;
        uint32_t sB = sA + STAGE_A_BYTES;
        const __nv_bfloat16* a0p = Ag + (size_t)ar0 * KF + kt * BK + ac0 * 8;
        const __nv_bfloat16* a1p = Ag + (size_t)ar1 * KF + kt * BK + ac1 * 8;
        const __nv_bfloat16* b0p = Bg + (size_t)ar0 * KF + kt * BK + ac0 * 8;
        const __nv_bfloat16* b1p = Bg + (size_t)ar1 * KF + kt * BK + ac1 * 8;
        cp16(sA + dA0, a0p);
        cp16(sA + dA1, a1p);
        cp16(sB + dA0, b0p);
        cp16(sB + dA1, b1p);
        asm volatile("cp.async.commit_group;" ::: "memory");
    };

    float acc[4][4][4];
    #pragma unroll
    for (int mt = 0; mt < 4; mt++)
        #pragma unroll
        for (int nt = 0; nt < 4; nt++)
            #pragma unroll
            for (int c = 0; c < 4; c++) acc[mt][nt][c] = 0.f;

    // fragment smem addresses (depend only on lane)
    const int frow = lane & 15;           // row within 16-row tile
    const int fch  = lane >> 4;           // k-half chunk add-on

    issue(0, 0);
    issue(1, 1);

    #pragma unroll 1
    for (int kt = 0; kt < NSLABS; kt++) {
        if (kt + 2 < NSLABS) issue((kt + 2) % STAGES, kt + 2);
        if (kt < NSLABS - 2)
            asm volatile("cp.async.wait_group 2;" ::: "memory");
        else if (kt == NSLABS - 2)
            asm volatile("cp.async.wait_group 1;" ::: "memory");
        else
            asm volatile("cp.async.wait_group 0;" ::: "memory");
        __syncthreads();

        const uint32_t sA = sbase + (kt % STAGES) * STAGE_BYTES;
        const uint32_t sB = sA + STAGE_A_BYTES;

        #pragma unroll
        for (int ks = 0; ks < 2; ks++) {
            uint32_t afr[4][4], br[2][4];
            const int ch = ks * 2 + fch;     // 16B chunk column 0..3
            #pragma unroll
            for (int mt = 0; mt < 4; mt++) {
                int r = wm + mt * 16 + frow;
                uint32_t addr = sA + r * 64 + ((ch ^ ((r >> 1) & 3)) << 4);
                ldsm_x4(addr, afr[mt][0], afr[mt][1], afr[mt][2], afr[mt][3]);
            }
            #pragma unroll
            for (int g = 0; g < 2; g++) {
                int r = wn + g * 16 + frow;
                uint32_t addr = sB + r * 64 + ((ch ^ ((r >> 1) & 3)) << 4);
                ldsm_x4(addr, br[g][0], br[g][1], br[g][2], br[g][3]);
            }
            #pragma unroll
            for (int mt = 0; mt < 4; mt++)
                #pragma unroll
                for (int nt = 0; nt < 4; nt++) {
                    const int g = nt >> 1, h = nt & 1;
                    asm volatile(
                        "mma.sync.aligned.m16n8k16.row.col.f32.bf16.bf16.f32 "
                        "{%0,%1,%2,%3}, {%4,%5,%6,%7}, {%8,%9}, {%0,%1,%2,%3};\n"
                        : "+f"(acc[mt][nt][0]), "+f"(acc[mt][nt][1]),
                          "+f"(acc[mt][nt][2]), "+f"(acc[mt][nt][3])
                        : "r"(afr[mt][0]), "r"(afr[mt][1]),
                          "r"(afr[mt][2]), "r"(afr[mt][3]),
                          "r"(br[g][h]), "r"(br[g][h + 2]));
                }
        }
        __syncthreads();   // protect stage buffer before it is re-issued
    }

    // epilogue: d2 = q2 + s2 - 2*dot
    #pragma unroll
    for (int mt = 0; mt < 4; mt++) {
        int rlo = m0 + wm + mt * 16 + (lane >> 2);
        float q2lo = g_q2[rlo];
        float q2hi = g_q2[rlo + 8];
        #pragma unroll
        for (int nt = 0; nt < 4; nt++) {
            int nc = n0 + wn + nt * 8 + (lane & 3) * 2;
            float s20 = g_s2[nc], s21 = g_s2[nc + 1];
            float2 o;
            o.x = q2lo + s20 - 2.f * acc[mt][nt][0];
            o.y = q2lo + s21 - 2.f * acc[mt][nt][1];
            *(float2*)(g_d2 + (size_t)rlo * NS + nc) = o;
            o.x = q2hi + s20 - 2.f * acc[mt][nt][2];
            o.y = q2hi + s21 - 2.f * acc[mt][nt][3];
            *(float2*)(g_d2 + (size_t)(rlo + 8) * NS + nc) = o;
        }
    }
}

// ---------------------------------------------------------------------------
// Kernel 3: per-query approx top-16 -> threshold -> candidate list.
// ---------------------------------------------------------------------------
__global__ __launch_bounds__(256)
void topk_select_kernel() {
    const int qrow = blockIdx.x;
    const int tid  = threadIdx.x;
    const float* row = g_d2 + (size_t)qrow * NS;

    float lv[KSEL];
    int   li[KSEL];
    #pragma unroll
    for (int i = 0; i < KSEL; i++) { lv[i] = CUDART_INF_F; li[i] = 0x7fffffff; }
    float worst = CUDART_INF_F;

    const float4* row4 = (const float4*)row;
    for (int j4 = tid; j4 < NS / 4; j4 += 256) {
        float4 v4 = row4[j4];
        float vs[4] = {v4.x, v4.y, v4.z, v4.w};
        #pragma unroll
        for (int c = 0; c < 4; c++) {
            float v = vs[c];
            if (v < worst) {
                int j = j4 * 4 + c;
                int pos = KSEL - 1;
                #pragma unroll
                for (int t = KSEL - 1; t > 0; t--) {
                    if (pos == t && v < lv[t - 1]) {
                        lv[t] = lv[t - 1]; li[t] = li[t - 1]; pos = t - 1;
                    }
                }
                lv[pos] = v; li[pos] = j;
                worst = lv[KSEL - 1];
            }
        }
    }

    __shared__ float sv[256];
    __shared__ int   si[256];
    __shared__ float T_s;
    __shared__ int   cnt;

    int p = 0;
    for (int r = 0; r < KSEL; r++) {
        sv[tid] = (p < KSEL) ? lv[p] : CUDART_INF_F;
        si[tid] = (p < KSEL) ? li[p] : 0x7fffffff;
        __syncthreads();
        #pragma unroll
        for (int s = 128; s > 0; s >>= 1) {
            if (tid < s) {
                float v2 = sv[tid + s]; int i2 = si[tid + s];
                if (v2 < sv[tid] || (v2 == sv[tid] && i2 < si[tid])) {
                    sv[tid] = v2; si[tid] = i2;
                }
            }
            __syncthreads();
        }
        int winIdx = si[0];
        if (r == KSEL - 1 && tid == 0) { T_s = sv[0]; cnt = 0; }
        if (p < KSEL && li[p] == winIdx) p++;
        __syncthreads();
    }

    const float thresh = T_s + MARGIN;
    for (int j4 = tid; j4 < NS / 4; j4 += 256) {
        float4 v4 = row4[j4];
        float vs[4] = {v4.x, v4.y, v4.z, v4.w};
        #pragma unroll
        for (int c = 0; c < 4; c++) {
            if (vs[c] <= thresh) {
                int slot = atomicAdd(&cnt, 1);
                if (slot < NCAND) g_cand[(size_t)qrow * NCAND + slot] = j4 * 4 + c;
            }
        }
    }
    __syncthreads();
    if (tid == 0) g_ccount[qrow] = (cnt < NCAND) ? cnt : NCAND;
}

// ---------------------------------------------------------------------------
// Kernel 4: exact fp32 refinement + final top-16 + weights.
// Output layout (float32): [ indices (NQ*16) | weights (NQ*16) ]
// ---------------------------------------------------------------------------
__global__ __launch_bounds__(256)
void refine_kernel(const float* __restrict__ q,
                   const float* __restrict__ s,
                   float* __restrict__ out) {
    const int qrow = blockIdx.x;
    const int tid  = threadIdx.x;
    const int warp = tid >> 5;
    const int lane = tid & 31;

    __shared__ float qs[KF];
    __shared__ float ev[NCAND];
    __shared__ int   ei[NCAND];
    __shared__ float sv[128];
    __shared__ int   si[128];
    __shared__ float resv[KSEL];
    __shared__ int   resi[KSEL];

    const int m = g_ccount[qrow];

    for (int i = tid; i < KF; i += 256) qs[i] = q[(size_t)qrow * KF + i];
    for (int i = tid; i < NCAND; i += 256) { ev[i] = CUDART_INF_F; ei[i] = 0x7fffffff; }
    __syncthreads();

    const float q2v = g_q2[qrow];
    for (int ci = warp; ci < m; ci += 8) {
        int sidx = g_cand[(size_t)qrow * NCAND + ci];
        const float* srow = s + (size_t)sidx * KF;
        float dot = 0.f;
        #pragma unroll
        for (int t = 0; t < KF / 32; t++)
            dot = fmaf(qs[lane + 32 * t], srow[lane + 32 * t], dot);
        #pragma unroll
        for (int o = 16; o; o >>= 1) dot += __shfl_down_sync(0xffffffffu, dot, o);
        if (lane == 0) {
            ev[ci] = q2v + g_s2[sidx] - 2.f * dot;
            ei[ci] = sidx;
        }
    }
    __syncthreads();

    for (int r = 0; r < KSEL; r++) {
        if (tid < 128) { sv[tid] = ev[tid]; si[tid] = ei[tid]; }
        __syncthreads();
        #pragma unroll
        for (int st = 64; st > 0; st >>= 1) {
            if (tid < st) {
                float v2 = sv[tid + st]; int i2 = si[tid + st];
                if (v2 < sv[tid] || (v2 == sv[tid] && i2 < si[tid])) {
                    sv[tid] = v2; si[tid] = i2;
                }
            }
            __syncthreads();
        }
        if (tid == 0) { resv[r] = sv[0]; resi[r] = si[0]; }
        __syncthreads();
        if (tid < 128 && ei[tid] == si[0]) ev[tid] = CUDART_INF_F;
        __syncthreads();
    }

    if (tid == 0) {
        float w[KSEL];
        float ssum = 0.f;
        #pragma unroll
        for (int r = 0; r < KSEL; r++) {
            float d = sqrtf(fmaxf(resv[r], 1e-12f));
            w[r] = 1.f / (d + 1e-6f);
            ssum += w[r];
        }
        float inv = 1.f / ssum;
        #pragma unroll
        for (int r = 0; r < KSEL; r++) {
            out[(size_t)qrow * KSEL + r] = (float)resi[r];
            out[(size_t)NQ * KSEL + (size_t)qrow * KSEL + r] = w[r] * inv;
        }
    }
}

// ---------------------------------------------------------------------------
extern "C" void kernel_launch(void* const* d_in, const int* in_sizes, int n_in,
                              void* d_out, int out_size) {
    const float* q = (const float*)d_in[0];  // (2048, 32, 16) -> (2048, 512)
    const float* s = (const float*)d_in[1];  // (65536, 32, 16) -> (65536, 512)
    float* out = (float*)d_out;

    static bool attr_done = false;
    if (!attr_done) {
        cudaFuncSetAttribute(dist_gemm,
                             cudaFuncAttributeMaxDynamicSharedMemorySize,
                             GEMM_DYN_SMEM);
        attr_done = true;
    }

    // 0) fp32 -> bf16 conversion
    {
        size_t tot = ((size_t)NQ + NS) * KF / 4;
        int nb = (int)((tot + 255) / 256);
        convert_kernel<<<nb, 256>>>(q, s);
    }

    // 1) exact fp32 norms
    int rows = NQ + NS;
    int nblocks = (rows * 32 + 255) / 256;
    norms_kernel<<<nblocks, 256>>>(q, s);

    // 2) approx distance GEMM. grid.x = M blocks (fast) -> B reuse in L2.
    dim3 g(NQ / BM, NS / BN);
    dist_gemm<<<g, 256, GEMM_DYN_SMEM>>>();

    // 3) approx top-16 + candidate collection
    topk_select_kernel<<<NQ, 256>>>();

    // 4) exact refinement + output
    refine_kernel<<<NQ, 256>>>(q, s, out);
}